// round 16
// baseline (speedup 1.0000x reference)
#include <cuda_runtime.h>
#include <cuda_bf16.h>
#include <math.h>

// Problem constants (fixed by setup_inputs)
#define NPTS 32768
#define NV   10475
#define NJ   55
#define KNN  6

// 2D (x,y) binning (R10/R13/R14-verified prep)
#define NBX  128
#define NBY  128
#define NB2  (NBX * NBY)         // 16384
#define BW   0.15625f            // 20/128, exact in fp32
#define BINV2 6.4f
#define XLIM 10.0f
#define SEPS 1e-3f               // screen slack in s-units
#define DELTA0 0.36f             // ~= sqrt(median d6)

typedef unsigned long long u64;
#define KSENT 0xFFFFFFFFFFFFFFFFull

// Scratch (no cudaMalloc allowed).
__device__ int    g_tcnt[NB2], g_tstart[NB2 + 1], g_tcur[NB2];
__device__ int    g_pcnt[NB2], g_pstart[NB2 + 1], g_pcur[NB2];
__device__ float4 g_tsorted[NV + 32];    // {x, y, z, -t2/2}, L2-resident
__device__ int    g_tidx  [NV + 32];
__device__ float4 g_psorted[NPTS];       // {x, y, z, orig_point_idx}
__device__ int    g_knn_idx[NPTS * KNN];
__device__ float  g_knn_d  [NPTS * KNN];

__device__ __forceinline__ int bin1(float x) {
    return min(NBX - 1, max(0, (int)((x + XLIM) * BINV2)));
}

// Exact reference-rounded d2 (verified R3-R15), clamped BEFORE selection,
// packed with the original index into a scan-order-independent sortable key.
__device__ __forceinline__ u64 cand_key(float4 t, int oidx,
                                        float px, float py, float pz, float p2) {
    float t2 = -2.0f * t.w;              // exact
    float cross = __fmaf_rn(pz, t.z, __fmaf_rn(py, t.y, __fmul_rn(px, t.x)));
    float d2 = fmaxf(__fmaf_rn(-2.0f, cross, __fadd_rn(p2, t2)), 0.0f);
    return ((u64)__float_as_uint(d2) << 32) | (u64)(unsigned)oidx;
}

__device__ __forceinline__ void key_insert(u64* K, u64 key) {
    if (key < K[KNN - 1]) {
        K[KNN - 1] = key;
#pragma unroll
        for (int k = KNN - 1; k > 0; --k)
            if (K[k] < K[k - 1]) { u64 t = K[k]; K[k] = K[k - 1]; K[k - 1] = t; }
    }
}

// Dedup-merge sorted-6 lists across lanes at shfl distance `off`.
__device__ __forceinline__ void merge_off(u64* K, int off) {
    u64 O[KNN];
#pragma unroll
    for (int k = 0; k < KNN; ++k)
        O[k] = __shfl_xor_sync(0xFFFFFFFFu, K[k], off);
    u64 R[KNN];
    int a = 0, b = 0;
#pragma unroll
    for (int k = 0; k < KNN; ++k) {
        u64 ka = (a < KNN) ? K[a] : KSENT;
        u64 kb = (b < KNN) ? O[b] : KSENT;
        if (ka == kb)      { R[k] = ka; ++a; ++b; }
        else if (ka < kb)  { R[k] = ka; ++a; }
        else               { R[k] = kb; ++b; }
    }
#pragma unroll
    for (int k = 0; k < KNN; ++k) K[k] = R[k];
}

__device__ __forceinline__ void merge_quad(u64* K) {
    merge_off(K, 1);
    merge_off(K, 2);
}

// ---------------------------------------------------------------------------
// Prep kernels (R10/R13-verified)
// ---------------------------------------------------------------------------
extern "C" __global__ void k_zero() {
    int i = blockIdx.x * blockDim.x + threadIdx.x;
    if (i < NB2) { g_tcnt[i] = 0; g_pcnt[i] = 0; }
}

extern "C" __global__ void k_hist(const float* __restrict__ tpts,
                                  const float* __restrict__ pts) {
    int i = blockIdx.x * blockDim.x + threadIdx.x;
    if (i < NV) {
        int bx = bin1(tpts[3*i]), by = bin1(tpts[3*i+1]);
        atomicAdd(&g_tcnt[bx * NBY + by], 1);
    }
    if (i < NPTS) {
        int kx = bin1(pts[3*i]), ky = bin1(pts[3*i+1]);
        if (kx & 1) ky = NBY - 1 - ky;           // serpentine for warp locality
        atomicAdd(&g_pcnt[kx * NBY + ky], 1);
    }
}

extern "C" __global__ void __launch_bounds__(1024) k_scan() {
    __shared__ int sA[1024], sB[1024];
    const int t = threadIdx.x;
    const int C = NB2 / 1024;                    // 16 cells per thread
#pragma unroll 1
    for (int w = 0; w < 2; ++w) {
        const int* cnt = w ? g_pcnt : g_tcnt;
        int* start = w ? g_pstart : g_tstart;
        int* cur   = w ? g_pcur   : g_tcur;
        int sum = 0;
        for (int i = 0; i < C; ++i) sum += cnt[t * C + i];
        sA[t] = sum; __syncthreads();
        int *src = sA, *dst = sB;
        for (int off = 1; off < 1024; off <<= 1) {
            int v = src[t] + ((t >= off) ? src[t - off] : 0);
            dst[t] = v; __syncthreads();
            int* tmp = src; src = dst; dst = tmp;
        }
        int run = src[t] - sum;
        for (int i = 0; i < C; ++i) {
            int id = t * C + i;
            start[id] = run; cur[id] = run;
            run += cnt[id];
        }
        if (t == 1023) start[NB2] = run;
        __syncthreads();
    }
}

extern "C" __global__ void k_scatter(const float* __restrict__ tpts,
                                     const float* __restrict__ pts) {
    int i = blockIdx.x * blockDim.x + threadIdx.x;
    if (i < NV) {
        float x = tpts[3*i], y = tpts[3*i+1], z = tpts[3*i+2];
        float t2 = __fadd_rn(__fadd_rn(__fmul_rn(x, x), __fmul_rn(y, y)),
                             __fmul_rn(z, z));
        int pos = atomicAdd(&g_tcur[bin1(x) * NBY + bin1(y)], 1);
        g_tsorted[pos] = make_float4(x, y, z, -0.5f * t2);
        g_tidx[pos] = i;
    }
    if (i >= NV && i < NV + 32) {                // pad
        g_tsorted[i] = make_float4(0.f, 0.f, 0.f, -INFINITY);
        g_tidx[i] = 0;
    }
    if (i < NPTS) {
        float x = pts[3*i], y = pts[3*i+1], z = pts[3*i+2];
        int kx = bin1(x), ky = bin1(y);
        if (kx & 1) ky = NBY - 1 - ky;
        int pos = atomicAdd(&g_pcur[kx * NBY + ky], 1);
        g_psorted[pos] = make_float4(x, y, z, __uint_as_float((unsigned)i));
    }
}

// ---------------------------------------------------------------------------
// Quad-split segment scan on GLOBAL (L2-resident) templates. Warp-uniform
// addresses -> every LDG.128 is a single broadcast request.
// ---------------------------------------------------------------------------
__device__ __forceinline__ void scan_quad(
    int s, int e, int par,
    float px, float py, float pz, float p2, u64* K, float& s_thresh)
{
    int bcnt = 0;
#pragma unroll 1
    for (int v0 = s + (par << 3); v0 < e; v0 += 32) {
        float sc[8];
#pragma unroll
        for (int i = 0; i < 8; ++i) {
            float4 t = __ldg(&g_tsorted[v0 + i]);    // pad covers overread
            float v = fmaf(pz, t.z, fmaf(py, t.y, fmaf(px, t.x, t.w)));
            sc[i] = (v0 + i < e) ? v : -INFINITY;
        }
        float m = fmaxf(fmaxf(fmaxf(sc[0], sc[1]), fmaxf(sc[2], sc[3])),
                        fmaxf(fmaxf(sc[4], sc[5]), fmaxf(sc[6], sc[7])));
        if (m > s_thresh) {
            unsigned pm = 0;
#pragma unroll
            for (int i = 0; i < 8; ++i)
                pm |= (sc[i] > s_thresh) ? (1u << i) : 0u;
            while (pm) {
                int i = __ffs(pm) - 1; pm &= pm - 1;
                key_insert(K, cand_key(__ldg(&g_tsorted[v0 + i]),
                                       __ldg(&g_tidx[v0 + i]),
                                       px, py, pz, p2));
            }
        }
        if (((++bcnt) & 3) == 0 && K[KNN - 1] != KSENT) {
            float d6 = __uint_as_float((unsigned)(K[KNN - 1] >> 32));
            s_thresh = fmaf(-0.5f, d6, 0.5f * p2) - SEPS;
        }
    }
    if (K[KNN - 1] != KSENT) {
        float d6 = __uint_as_float((unsigned)(K[KNN - 1] >> 32));
        s_thresh = fmaf(-0.5f, d6, 0.5f * p2) - SEPS;
    }
}

// ---------------------------------------------------------------------------
// Kernel B: 2D-windowed KNN, 4 threads/point, NO smem staging.
// 512 CTAs x 256 threads = 131K threads, ~4 CTAs/SM -> ~8 warps/SMSP,
// single wave. Window schedule = R13/R14 (delta0 + adaptive extension).
// ---------------------------------------------------------------------------
extern "C" __global__ void __launch_bounds__(256)
k_knn()
{
    const int n   = blockIdx.x * 64 + (threadIdx.x >> 2);
    const int par = threadIdx.x & 3;
    float4 P = g_psorted[n];
    float px = P.x, py = P.y, pz = P.z;
    unsigned pid = __float_as_uint(P.w);
    float p2 = __fadd_rn(__fadd_rn(__fmul_rn(px, px), __fmul_rn(py, py)),
                         __fmul_rn(pz, pz));

    // warp (x,y) hull (8 distinct points; quad lanes duplicate harmlessly)
    float xlo = px, xhi = px, ylo = py, yhi = py;
#pragma unroll
    for (int off = 16; off >= 1; off >>= 1) {
        xlo = fminf(xlo, __shfl_xor_sync(0xFFFFFFFFu, xlo, off));
        xhi = fmaxf(xhi, __shfl_xor_sync(0xFFFFFFFFu, xhi, off));
        ylo = fminf(ylo, __shfl_xor_sync(0xFFFFFFFFu, ylo, off));
        yhi = fmaxf(yhi, __shfl_xor_sync(0xFFFFFFFFu, yhi, off));
    }

    u64 K[KNN];
#pragma unroll
    for (int k = 0; k < KNN; ++k) K[k] = KSENT;
    float s_thresh = -INFINITY;

    float delta = DELTA0;
    int bxlo = bin1(xlo - delta), bxhi = bin1(xhi + delta);
    int bylo = bin1(ylo - delta), byhi = bin1(yhi + delta);

    for (int bx = bxlo; bx <= bxhi; ++bx) {
        int s = __ldg(&g_tstart[bx * NBY + bylo]);
        int e = __ldg(&g_tstart[bx * NBY + byhi + 1]);
        scan_quad(s, e, par, px, py, pz, p2, K, s_thresh);
    }

#pragma unroll 1
    for (int it = 0; it < 12; ++it) {
        merge_quad(K);                           // true top-6 over window
        float bx_lo = (bxlo == 0)       ? 1e15f : px - ((float)bxlo * BW - XLIM);
        float bx_hi = (bxhi == NBX - 1) ? 1e15f : ((float)(bxhi + 1) * BW - XLIM) - px;
        float by_lo = (bylo == 0)       ? 1e15f : py - ((float)bylo * BW - XLIM);
        float by_hi = (byhi == NBY - 1) ? 1e15f : ((float)(byhi + 1) * BW - XLIM) - py;
        float bound = fminf(fminf(bx_lo, bx_hi), fminf(by_lo, by_hi));
        float d6 = __uint_as_float((unsigned)(K[KNN - 1] >> 32));
        bool have6 = (K[KNN - 1] != KSENT);
        bool done = have6 && (d6 <= 0.998f * bound * bound);
        if (__all_sync(0xFFFFFFFFu, done)) break;

        float need = have6 ? (__fsqrt_rn(d6) * 1.002f) : (delta * 2.0f);
#pragma unroll
        for (int off = 16; off >= 1; off >>= 1)
            need = fmaxf(need, __shfl_xor_sync(0xFFFFFFFFu, need, off));
        delta = fmaxf(need, delta + BW);         // monotone growth >= 1 bin

        int nbxlo = bin1(xlo - delta), nbxhi = bin1(xhi + delta);
        int nbylo = bin1(ylo - delta), nbyhi = bin1(yhi + delta);

        for (int bx = nbxlo; bx < bxlo; ++bx) {
            int s = __ldg(&g_tstart[bx * NBY + nbylo]);
            int e = __ldg(&g_tstart[bx * NBY + nbyhi + 1]);
            scan_quad(s, e, par, px, py, pz, p2, K, s_thresh);
        }
        for (int bx = bxhi + 1; bx <= nbxhi; ++bx) {
            int s = __ldg(&g_tstart[bx * NBY + nbylo]);
            int e = __ldg(&g_tstart[bx * NBY + nbyhi + 1]);
            scan_quad(s, e, par, px, py, pz, p2, K, s_thresh);
        }
        if (nbylo < bylo)
            for (int bx = bxlo; bx <= bxhi; ++bx) {
                int s = __ldg(&g_tstart[bx * NBY + nbylo]);
                int e = __ldg(&g_tstart[bx * NBY + bylo]);
                scan_quad(s, e, par, px, py, pz, p2, K, s_thresh);
            }
        if (nbyhi > byhi)
            for (int bx = bxlo; bx <= bxhi; ++bx) {
                int s = __ldg(&g_tstart[bx * NBY + byhi + 1]);
                int e = __ldg(&g_tstart[bx * NBY + nbyhi + 1]);
                scan_quad(s, e, par, px, py, pz, p2, K, s_thresh);
            }
        bxlo = nbxlo; bxhi = nbxhi; bylo = nbylo; byhi = nbyhi;
    }
    merge_quad(K);                               // covers loop-exhaust exit

    if (par == 0) {
#pragma unroll
        for (int k = 0; k < KNN; ++k) {
            g_knn_idx[pid * KNN + k] = (int)(unsigned)(K[k] & 0xFFFFFFFFull);
            g_knn_d  [pid * KNN + k] = __uint_as_float((unsigned)(K[k] >> 32));
        }
    }
}

// ---------------------------------------------------------------------------
// Epilogue (unchanged, measured 17us). One warp = one point.
// ---------------------------------------------------------------------------
extern "C" __global__ void __launch_bounds__(256)
epilogue_kernel(const float* __restrict__ lbs,   // (V,55)
                const float* __restrict__ vt,    // (V,16)
                float* __restrict__ out)         // [N dist | N*16 transform]
{
    int gwarp = (blockIdx.x * blockDim.x + threadIdx.x) >> 5;
    int lane  = threadIdx.x & 31;

    int   idx[KNN];
    float d[KNN];
#pragma unroll
    for (int k = 0; k < KNN; ++k) {
        idx[k] = g_knn_idx[gwarp * KNN + k];
        d[k]   = g_knn_d  [gwarp * KNN + k];
    }

    const float* w0row = lbs + (long)idx[0] * NJ;
    float w0a = w0row[lane];
    float w0b = (lane < NJ - 32) ? w0row[lane + 32] : 0.0f;

    float conf[KNN];
    conf[0] = 1.0f;
#pragma unroll
    for (int k = 1; k < KNN; ++k) {
        const float* wr = lbs + (long)idx[k] * NJ;
        float a = fabsf(wr[lane] - w0a);
        if (lane < NJ - 32) a += fabsf(wr[lane + 32] - w0b);
#pragma unroll
        for (int off = 16; off >= 1; off >>= 1)
            a += __shfl_xor_sync(0xFFFFFFFFu, a, off);
        conf[k] = (expf(-a * (1.0f / 0.02f)) > 0.9f) ? 1.0f : 0.0f;
    }

    float w[KNN];
    float wsum = 0.0f;
#pragma unroll
    for (int k = 0; k < KNN; ++k) {
        w[k] = expf(-d[k]) * conf[k];
        wsum += w[k];
    }
    float inv = 1.0f / wsum;

    float xd  = 0.0f;
    float acc = 0.0f;
#pragma unroll
    for (int k = 0; k < KNN; ++k) {
        float wk = w[k] * inv;
        xd = fmaf(wk, d[k], xd);
        if (lane < 16)
            acc = fmaf(wk, vt[(long)idx[k] * 16 + lane], acc);
    }

    if (lane == 0) out[gwarp] = xd;
    if (lane < 16) out[NPTS + gwarp * 16 + lane] = acc;
}

// ---------------------------------------------------------------------------
// Launch. Inputs: lbs_weights, verts_transform, points, template_points, K.
// ---------------------------------------------------------------------------
extern "C" void kernel_launch(void* const* d_in, const int* in_sizes, int n_in,
                              void* d_out, int out_size)
{
    const float* lbs  = (const float*)d_in[0];
    const float* vt   = (const float*)d_in[1];
    const float* pts  = (const float*)d_in[2];
    const float* tpts = (const float*)d_in[3];
    float* out = (float*)d_out;

    k_zero<<<(NB2 + 255) / 256, 256>>>();
    k_hist<<<(NPTS + 255) / 256, 256>>>(tpts, pts);
    k_scan<<<1, 1024>>>();
    k_scatter<<<(NPTS + 255) / 256, 256>>>(tpts, pts);
    k_knn<<<NPTS / 64, 256>>>();
    epilogue_kernel<<<(NPTS * 32) / 256, 256>>>(lbs, vt, out);
}

// round 17
// speedup vs baseline: 1.4543x; 1.4543x over previous
#include <cuda_runtime.h>
#include <cuda_bf16.h>
#include <math.h>

// Problem constants (fixed by setup_inputs)
#define NPTS 32768
#define NV   10475
#define NJ   55
#define KNN  6

// 2D (x,y) binning (R10/R13/R14-verified prep)
#define NBX  128
#define NBY  128
#define NB2  (NBX * NBY)         // 16384
#define BW   0.15625f            // 20/128, exact in fp32
#define BINV2 6.4f
#define XLIM 10.0f
#define SEPS 1e-3f               // screen slack in s-units
#define DELTA0 0.36f             // ~= sqrt(median d6)

typedef unsigned long long u64;
#define KSENT 0xFFFFFFFFFFFFFFFFull

// Scratch (no cudaMalloc allowed).
__device__ int    g_tcnt[NB2], g_tstart[NB2 + 1], g_tcur[NB2];
__device__ int    g_pcnt[NB2], g_pstart[NB2 + 1], g_pcur[NB2];
__device__ float4 g_tsorted[NV + 16];    // {x, y, z, -t2/2}
__device__ int    g_tidx  [NV + 16];
__device__ float4 g_psorted[NPTS];       // {x, y, z, orig_point_idx}
__device__ int    g_knn_idx[NPTS * KNN];
__device__ float  g_knn_d  [NPTS * KNN];

__device__ __forceinline__ int bin1(float x) {
    return min(NBX - 1, max(0, (int)((x + XLIM) * BINV2)));
}

// Exact reference-rounded d2 (verified R3-R16), clamped BEFORE selection,
// packed with the original index into a scan-order-independent sortable key.
__device__ __forceinline__ u64 cand_key(float4 t, int oidx,
                                        float px, float py, float pz, float p2) {
    float t2 = -2.0f * t.w;              // exact
    float cross = __fmaf_rn(pz, t.z, __fmaf_rn(py, t.y, __fmul_rn(px, t.x)));
    float d2 = fmaxf(__fmaf_rn(-2.0f, cross, __fadd_rn(p2, t2)), 0.0f);
    return ((u64)__float_as_uint(d2) << 32) | (u64)(unsigned)oidx;
}

__device__ __forceinline__ void key_insert(u64* K, u64 key) {
    if (key < K[KNN - 1]) {
        K[KNN - 1] = key;
#pragma unroll
        for (int k = KNN - 1; k > 0; --k)
            if (K[k] < K[k - 1]) { u64 t = K[k]; K[k] = K[k - 1]; K[k - 1] = t; }
    }
}

// Dedup-merge the pair's sorted lists (keys unique per candidate; equal keys
// collapse). Safe to call repeatedly (idempotent on merged lists).
__device__ __forceinline__ void merge_pair(u64* K) {
    u64 O[KNN];
#pragma unroll
    for (int k = 0; k < KNN; ++k)
        O[k] = __shfl_xor_sync(0xFFFFFFFFu, K[k], 1);
    u64 R[KNN];
    int a = 0, b = 0;
#pragma unroll
    for (int k = 0; k < KNN; ++k) {
        u64 ka = (a < KNN) ? K[a] : KSENT;
        u64 kb = (b < KNN) ? O[b] : KSENT;
        if (ka == kb)      { R[k] = ka; ++a; ++b; }
        else if (ka < kb)  { R[k] = ka; ++a; }
        else               { R[k] = kb; ++b; }
    }
#pragma unroll
    for (int k = 0; k < KNN; ++k) K[k] = R[k];
}

// ---------------------------------------------------------------------------
// Prep kernels (R10/R13/R14-verified)
// ---------------------------------------------------------------------------
extern "C" __global__ void k_zero() {
    int i = blockIdx.x * blockDim.x + threadIdx.x;
    if (i < NB2) { g_tcnt[i] = 0; g_pcnt[i] = 0; }
}

extern "C" __global__ void k_hist(const float* __restrict__ tpts,
                                  const float* __restrict__ pts) {
    int i = blockIdx.x * blockDim.x + threadIdx.x;
    if (i < NV) {
        int bx = bin1(tpts[3*i]), by = bin1(tpts[3*i+1]);
        atomicAdd(&g_tcnt[bx * NBY + by], 1);
    }
    if (i < NPTS) {
        int kx = bin1(pts[3*i]), ky = bin1(pts[3*i+1]);
        if (kx & 1) ky = NBY - 1 - ky;           // serpentine for warp locality
        atomicAdd(&g_pcnt[kx * NBY + ky], 1);
    }
}

extern "C" __global__ void __launch_bounds__(1024) k_scan() {
    __shared__ int sA[1024], sB[1024];
    const int t = threadIdx.x;
    const int C = NB2 / 1024;                    // 16 cells per thread
#pragma unroll 1
    for (int w = 0; w < 2; ++w) {
        const int* cnt = w ? g_pcnt : g_tcnt;
        int* start = w ? g_pstart : g_tstart;
        int* cur   = w ? g_pcur   : g_tcur;
        int sum = 0;
        for (int i = 0; i < C; ++i) sum += cnt[t * C + i];
        sA[t] = sum; __syncthreads();
        int *src = sA, *dst = sB;
        for (int off = 1; off < 1024; off <<= 1) {
            int v = src[t] + ((t >= off) ? src[t - off] : 0);
            dst[t] = v; __syncthreads();
            int* tmp = src; src = dst; dst = tmp;
        }
        int run = src[t] - sum;
        for (int i = 0; i < C; ++i) {
            int id = t * C + i;
            start[id] = run; cur[id] = run;
            run += cnt[id];
        }
        if (t == 1023) start[NB2] = run;
        __syncthreads();
    }
}

extern "C" __global__ void k_scatter(const float* __restrict__ tpts,
                                     const float* __restrict__ pts) {
    int i = blockIdx.x * blockDim.x + threadIdx.x;
    if (i < NV) {
        float x = tpts[3*i], y = tpts[3*i+1], z = tpts[3*i+2];
        float t2 = __fadd_rn(__fadd_rn(__fmul_rn(x, x), __fmul_rn(y, y)),
                             __fmul_rn(z, z));
        int pos = atomicAdd(&g_tcur[bin1(x) * NBY + bin1(y)], 1);
        g_tsorted[pos] = make_float4(x, y, z, -0.5f * t2);
        g_tidx[pos] = i;
    }
    if (i >= NV && i < NV + 16) {                // pad
        g_tsorted[i] = make_float4(0.f, 0.f, 0.f, -INFINITY);
        g_tidx[i] = 0;
    }
    if (i < NPTS) {
        float x = pts[3*i], y = pts[3*i+1], z = pts[3*i+2];
        int kx = bin1(x), ky = bin1(y);
        if (kx & 1) ky = NBY - 1 - ky;
        int pos = atomicAdd(&g_pcur[kx * NBY + ky], 1);
        g_psorted[pos] = make_float4(x, y, z, __uint_as_float((unsigned)i));
    }
}

// ---------------------------------------------------------------------------
// Pair-split segment scan (R14-verified) with per-batch threshold refresh.
// ---------------------------------------------------------------------------
__device__ __forceinline__ void scan_pair(
    const float4* __restrict__ st, const int* __restrict__ stidx,
    int s, int e, int par,
    float px, float py, float pz, float p2, u64* K, float& s_thresh)
{
#pragma unroll 1
    for (int v0 = s + (par << 3); v0 < e; v0 += 16) {
        float sc[8];
#pragma unroll
        for (int i = 0; i < 8; ++i) {
            float4 t = st[v0 + i];                   // pad covers overread
            float v = fmaf(pz, t.z, fmaf(py, t.y, fmaf(px, t.x, t.w)));
            sc[i] = (v0 + i < e) ? v : -INFINITY;
        }
        float m = fmaxf(fmaxf(fmaxf(sc[0], sc[1]), fmaxf(sc[2], sc[3])),
                        fmaxf(fmaxf(sc[4], sc[5]), fmaxf(sc[6], sc[7])));
        if (m > s_thresh) {
            unsigned pm = 0;
#pragma unroll
            for (int i = 0; i < 8; ++i)
                pm |= (sc[i] > s_thresh) ? (1u << i) : 0u;
            while (pm) {
                int i = __ffs(pm) - 1; pm &= pm - 1;
                key_insert(K, cand_key(st[v0 + i], stidx[v0 + i],
                                       px, py, pz, p2));
            }
            if (K[KNN - 1] != KSENT) {               // refresh every batch
                float d6 = __uint_as_float((unsigned)(K[KNN - 1] >> 32));
                s_thresh = fmaxf(s_thresh,
                                 fmaf(-0.5f, d6, 0.5f * p2) - SEPS);
            }
        }
    }
}

// ---------------------------------------------------------------------------
// Kernel B: 2D-windowed KNN, 2 threads/point, 512-thread CTAs (R14 champion)
// + home-bin threshold warm-up (insert-path suppression).
// ---------------------------------------------------------------------------
extern "C" __global__ void __launch_bounds__(512, 1)
k_knn()
{
    extern __shared__ char smem[];
    float4* st    = (float4*)smem;               // NV+16
    int*    stidx = (int*)(st + NV + 16);        // NV+16

    for (int i = threadIdx.x; i < NV + 16; i += 512) {
        st[i] = g_tsorted[i]; stidx[i] = g_tidx[i];
    }
    __syncthreads();

    const int n   = blockIdx.x * 256 + (threadIdx.x >> 1);
    const int par = threadIdx.x & 1;
    float4 P = g_psorted[n];
    float px = P.x, py = P.y, pz = P.z;
    unsigned pid = __float_as_uint(P.w);
    float p2 = __fadd_rn(__fadd_rn(__fmul_rn(px, px), __fmul_rn(py, py)),
                         __fmul_rn(pz, pz));

    // ---- Home-bin warm-up: seed s_thresh from the 6 best screen scores ----
    // (K untouched: home bin is re-scanned normally inside the window, so no
    //  duplicate keys. Threshold is conservative: s6_home <= s6_true, and
    //  SEPS >> s-vs-d2 rounding skew.)
    float s_thresh = -INFINITY;
    {
        int hb = bin1(px) * NBY + bin1(py);
        int hs = __ldg(&g_tstart[hb]), he = __ldg(&g_tstart[hb + 1]);
        float w[KNN];
#pragma unroll
        for (int k = 0; k < KNN; ++k) w[k] = -INFINITY;
        int cnt = he - hs;
#pragma unroll 1
        for (int j = hs; j < he; ++j) {
            float4 t = st[j];
            float v = fmaf(pz, t.z, fmaf(py, t.y, fmaf(px, t.x, t.w)));
            if (v > w[KNN - 1]) {
                w[KNN - 1] = v;
#pragma unroll
                for (int k = KNN - 1; k > 0; --k)
                    if (w[k] > w[k - 1]) { float tt = w[k]; w[k] = w[k-1]; w[k-1] = tt; }
            }
        }
        if (cnt >= KNN) s_thresh = w[KNN - 1] - SEPS;
    }

    // warp (x,y) hull (16 distinct points; pair lanes duplicate harmlessly)
    float xlo = px, xhi = px, ylo = py, yhi = py;
#pragma unroll
    for (int off = 16; off >= 1; off >>= 1) {
        xlo = fminf(xlo, __shfl_xor_sync(0xFFFFFFFFu, xlo, off));
        xhi = fmaxf(xhi, __shfl_xor_sync(0xFFFFFFFFu, xhi, off));
        ylo = fminf(ylo, __shfl_xor_sync(0xFFFFFFFFu, ylo, off));
        yhi = fmaxf(yhi, __shfl_xor_sync(0xFFFFFFFFu, yhi, off));
    }

    u64 K[KNN];
#pragma unroll
    for (int k = 0; k < KNN; ++k) K[k] = KSENT;

    float delta = DELTA0;
    int bxlo = bin1(xlo - delta), bxhi = bin1(xhi + delta);
    int bylo = bin1(ylo - delta), byhi = bin1(yhi + delta);

    for (int bx = bxlo; bx <= bxhi; ++bx) {
        int s = __ldg(&g_tstart[bx * NBY + bylo]);
        int e = __ldg(&g_tstart[bx * NBY + byhi + 1]);
        scan_pair(st, stidx, s, e, par, px, py, pz, p2, K, s_thresh);
    }

#pragma unroll 1
    for (int it = 0; it < 12; ++it) {
        merge_pair(K);                           // true top-6 over window
        float bx_lo = (bxlo == 0)       ? 1e15f : px - ((float)bxlo * BW - XLIM);
        float bx_hi = (bxhi == NBX - 1) ? 1e15f : ((float)(bxhi + 1) * BW - XLIM) - px;
        float by_lo = (bylo == 0)       ? 1e15f : py - ((float)bylo * BW - XLIM);
        float by_hi = (byhi == NBY - 1) ? 1e15f : ((float)(byhi + 1) * BW - XLIM) - py;
        float bound = fminf(fminf(bx_lo, bx_hi), fminf(by_lo, by_hi));
        float d6 = __uint_as_float((unsigned)(K[KNN - 1] >> 32));
        bool have6 = (K[KNN - 1] != KSENT);
        bool done = have6 && (d6 <= 0.998f * bound * bound);
        if (__all_sync(0xFFFFFFFFu, done)) break;

        float need = have6 ? (__fsqrt_rn(d6) * 1.002f) : (delta * 2.0f);
#pragma unroll
        for (int off = 16; off >= 1; off >>= 1)
            need = fmaxf(need, __shfl_xor_sync(0xFFFFFFFFu, need, off));
        delta = fmaxf(need, delta + BW);         // monotone growth >= 1 bin

        int nbxlo = bin1(xlo - delta), nbxhi = bin1(xhi + delta);
        int nbylo = bin1(ylo - delta), nbyhi = bin1(yhi + delta);

        for (int bx = nbxlo; bx < bxlo; ++bx) {
            int s = __ldg(&g_tstart[bx * NBY + nbylo]);
            int e = __ldg(&g_tstart[bx * NBY + nbyhi + 1]);
            scan_pair(st, stidx, s, e, par, px, py, pz, p2, K, s_thresh);
        }
        for (int bx = bxhi + 1; bx <= nbxhi; ++bx) {
            int s = __ldg(&g_tstart[bx * NBY + nbylo]);
            int e = __ldg(&g_tstart[bx * NBY + nbyhi + 1]);
            scan_pair(st, stidx, s, e, par, px, py, pz, p2, K, s_thresh);
        }
        if (nbylo < bylo)
            for (int bx = bxlo; bx <= bxhi; ++bx) {
                int s = __ldg(&g_tstart[bx * NBY + nbylo]);
                int e = __ldg(&g_tstart[bx * NBY + bylo]);
                scan_pair(st, stidx, s, e, par, px, py, pz, p2, K, s_thresh);
            }
        if (nbyhi > byhi)
            for (int bx = bxlo; bx <= bxhi; ++bx) {
                int s = __ldg(&g_tstart[bx * NBY + byhi + 1]);
                int e = __ldg(&g_tstart[bx * NBY + nbyhi + 1]);
                scan_pair(st, stidx, s, e, par, px, py, pz, p2, K, s_thresh);
            }
        bxlo = nbxlo; bxhi = nbxhi; bylo = nbylo; byhi = nbyhi;
    }
    merge_pair(K);                               // covers loop-exhaust exit

    if (par == 0) {
#pragma unroll
        for (int k = 0; k < KNN; ++k) {
            g_knn_idx[pid * KNN + k] = (int)(unsigned)(K[k] & 0xFFFFFFFFull);
            g_knn_d  [pid * KNN + k] = __uint_as_float((unsigned)(K[k] >> 32));
        }
    }
}

// ---------------------------------------------------------------------------
// Epilogue (unchanged, measured 17us). One warp = one point.
// ---------------------------------------------------------------------------
extern "C" __global__ void __launch_bounds__(256)
epilogue_kernel(const float* __restrict__ lbs,   // (V,55)
                const float* __restrict__ vt,    // (V,16)
                float* __restrict__ out)         // [N dist | N*16 transform]
{
    int gwarp = (blockIdx.x * blockDim.x + threadIdx.x) >> 5;
    int lane  = threadIdx.x & 31;

    int   idx[KNN];
    float d[KNN];
#pragma unroll
    for (int k = 0; k < KNN; ++k) {
        idx[k] = g_knn_idx[gwarp * KNN + k];
        d[k]   = g_knn_d  [gwarp * KNN + k];
    }

    const float* w0row = lbs + (long)idx[0] * NJ;
    float w0a = w0row[lane];
    float w0b = (lane < NJ - 32) ? w0row[lane + 32] : 0.0f;

    float conf[KNN];
    conf[0] = 1.0f;
#pragma unroll
    for (int k = 1; k < KNN; ++k) {
        const float* wr = lbs + (long)idx[k] * NJ;
        float a = fabsf(wr[lane] - w0a);
        if (lane < NJ - 32) a += fabsf(wr[lane + 32] - w0b);
#pragma unroll
        for (int off = 16; off >= 1; off >>= 1)
            a += __shfl_xor_sync(0xFFFFFFFFu, a, off);
        conf[k] = (expf(-a * (1.0f / 0.02f)) > 0.9f) ? 1.0f : 0.0f;
    }

    float w[KNN];
    float wsum = 0.0f;
#pragma unroll
    for (int k = 0; k < KNN; ++k) {
        w[k] = expf(-d[k]) * conf[k];
        wsum += w[k];
    }
    float inv = 1.0f / wsum;

    float xd  = 0.0f;
    float acc = 0.0f;
#pragma unroll
    for (int k = 0; k < KNN; ++k) {
        float wk = w[k] * inv;
        xd = fmaf(wk, d[k], xd);
        if (lane < 16)
            acc = fmaf(wk, vt[(long)idx[k] * 16 + lane], acc);
    }

    if (lane == 0) out[gwarp] = xd;
    if (lane < 16) out[NPTS + gwarp * 16 + lane] = acc;
}

// ---------------------------------------------------------------------------
// Launch. Inputs: lbs_weights, verts_transform, points, template_points, K.
// ---------------------------------------------------------------------------
extern "C" void kernel_launch(void* const* d_in, const int* in_sizes, int n_in,
                              void* d_out, int out_size)
{
    const float* lbs  = (const float*)d_in[0];
    const float* vt   = (const float*)d_in[1];
    const float* pts  = (const float*)d_in[2];
    const float* tpts = (const float*)d_in[3];
    float* out = (float*)d_out;

    const int smem_bytes = (NV + 16) * 16 + (NV + 16) * 4;   // ~210 KB
    cudaFuncSetAttribute(k_knn,
                         cudaFuncAttributeMaxDynamicSharedMemorySize,
                         smem_bytes);

    k_zero<<<(NB2 + 255) / 256, 256>>>();
    k_hist<<<(NPTS + 255) / 256, 256>>>(tpts, pts);
    k_scan<<<1, 1024>>>();
    k_scatter<<<(NPTS + 255) / 256, 256>>>(tpts, pts);
    k_knn<<<NPTS / 256, 512, smem_bytes>>>();
    epilogue_kernel<<<(NPTS * 32) / 256, 256>>>(lbs, vt, out);
}